// round 16
// baseline (speedup 1.0000x reference)
#include <cuda_runtime.h>
#include <cstdint>

// Idx2PixelLayer: bilinear gather of N=1e6 points from a 2048x2048x8 fp32 image.
// c = ((coord - 1) mod (dim - 4)) + 1   (non-negative mod, JAX semantics)
// out = w00*g(0,0) + w10*g(1,0) + w01*g(0,1) + w11*g(1,1)   (weights as below)
// Reference's off-mask is always false (c <= 2045 < 2048), so dropped.
//
// R14: fused two-phase partition. One block per 1024-pt chunk -> 977 blocks,
// ALL co-resident (<=1184 on 148 SMs), so every block executes phase 0
// (top-half image points) at the same time, then phase 1. Sweep reads coords
// ONCE (coalesced), splits ids+xy into two smem lists via ballot compaction
// (cheap bin = clamp((int)x)>>10; x<1 wrap points land in bin 0, processed
// exactly once -- correctness needs only "exactly once", locality loss is
// measure-zero). Each phase's grid-wide image window is 64MB -> L2-resident
// -> duplicate pixel hits dedup (R6 proved this halves image DRAM reads).
// Processing keeps the proven R2 gather shape: 2 threads/point, lane pair
// covers one 32B pixel sector per LDG.128, full lanes, coalesced __stcs out.

static constexpr int H = 2048;
static constexpr int W = 2048;
static constexpr int C = 8;

static constexpr int THREADS = 256;
static constexpr int CHUNK   = 1024;   // points per block
static constexpr int CAP     = 640;    // per-bin list slots (mean 512, sd 16)

__global__ __launch_bounds__(THREADS)
void idx2pixel_fused(const float2* __restrict__ coords,
                     const float*  __restrict__ visible,
                     float* __restrict__ out,
                     int n)
{
    __shared__ int    s_cnt[2];
    __shared__ int    s_id[2][CAP];
    __shared__ float2 s_xy[2][CAP];

    const int tid  = threadIdx.x;
    const int lane = tid & 31;
    const int p0   = blockIdx.x * CHUNK;
    const int RS   = W * C;
    const float m0 = (float)(H - 4), m1 = (float)(W - 4);

    if (tid < 2) s_cnt[tid] = 0;
    __syncthreads();

    // ---- sweep once: coalesced coord load + two-way ballot compaction ----
    #pragma unroll
    for (int r = 0; r < CHUNK; r += THREADS) {
        int p = p0 + r + tid;
        bool act = (p < n);
        float2 xy = act ? __ldg(coords + p) : make_float2(0.0f, 0.0f);

        // Cheap consistent bin: equals i0>>10 for x>=1; wrap cases -> bin 0.
        int bx  = min(max((int)xy.x, 0), H - 1);
        int bin = bx >> 10;

        #pragma unroll
        for (int b = 0; b < 2; b++) {
            bool match = act && (bin == b);
            unsigned m = __ballot_sync(0xffffffffu, match);
            int alloc = 0;
            if (m) {
                int leader = __ffs(m) - 1;
                if (lane == leader) alloc = atomicAdd(&s_cnt[b], __popc(m));
                alloc = __shfl_sync(0xffffffffu, alloc, leader);
            }
            if (match) {
                int slot = alloc + __popc(m & ((1u << lane) - 1u));
                if (slot < CAP) {
                    s_id[b][slot] = p;
                    s_xy[b][slot] = xy;
                } else {
                    // Statistically unreachable overflow: process inline now.
                    float c0 = fmodf(xy.x - 1.0f, m0); if (c0 < 0.0f) c0 += m0; c0 += 1.0f;
                    float c1 = fmodf(xy.y - 1.0f, m1); if (c1 < 0.0f) c1 += m1; c1 += 1.0f;
                    float f0 = floorf(c0), f1 = floorf(c1);
                    float d0 = c0 - f0,  d1 = c1 - f1;
                    int base = ((int)f0 * W + (int)f1) * C;
                    float w00 = d0*d1, w10 = (1.0f-d0)*d1;
                    float w01 = d0*(1.0f-d1), w11 = (1.0f-d0)*(1.0f-d1);
                    #pragma unroll
                    for (int k = 0; k < 2; k++) {
                        const float4* q00 = reinterpret_cast<const float4*>(visible + base + 4*k);
                        const float4* q01 = reinterpret_cast<const float4*>(visible + base + 4*k + C);
                        const float4* q10 = reinterpret_cast<const float4*>(visible + base + 4*k + RS);
                        const float4* q11 = reinterpret_cast<const float4*>(visible + base + 4*k + RS + C);
                        float4 a00 = __ldg(q00), a01 = __ldg(q01), a10 = __ldg(q10), a11 = __ldg(q11);
                        float4 o;
                        o.x = w00*a00.x + w10*a10.x + w01*a01.x + w11*a11.x;
                        o.y = w00*a00.y + w10*a10.y + w01*a01.y + w11*a11.y;
                        o.z = w00*a00.z + w10*a10.z + w01*a01.z + w11*a11.z;
                        o.w = w00*a00.w + w10*a10.w + w01*a01.w + w11*a11.w;
                        __stcs(reinterpret_cast<float4*>(out + p * C + 4*k), o);
                    }
                }
            }
        }
    }
    __syncthreads();

    // ---- process: phase 0 (top half) then phase 1; 2 threads/point ----
    const int k = tid & 1;                 // channel half: floats [4k, 4k+4)

    #pragma unroll
    for (int b = 0; b < 2; b++) {
        int cnt = min(s_cnt[b], CAP);
        for (int i = tid >> 1; i < cnt; i += THREADS / 2) {
            int    p  = s_id[b][i];
            float2 xy = s_xy[b][i];

            float c0 = fmodf(xy.x - 1.0f, m0); if (c0 < 0.0f) c0 += m0; c0 += 1.0f;
            float c1 = fmodf(xy.y - 1.0f, m1); if (c1 < 0.0f) c1 += m1; c1 += 1.0f;
            float f0 = floorf(c0), f1 = floorf(c1);
            float d0 = c0 - f0,  d1 = c1 - f1;
            int base = ((int)f0 * W + (int)f1) * C + 4 * k;

            const float4* q00 = reinterpret_cast<const float4*>(visible + base);
            const float4* q01 = reinterpret_cast<const float4*>(visible + base + C);
            const float4* q10 = reinterpret_cast<const float4*>(visible + base + RS);
            const float4* q11 = reinterpret_cast<const float4*>(visible + base + RS + C);

            float4 a00 = __ldg(q00);
            float4 a01 = __ldg(q01);
            float4 a10 = __ldg(q10);
            float4 a11 = __ldg(q11);

            float w00 = d0 * d1;
            float w10 = (1.0f - d0) * d1;
            float w01 = d0 * (1.0f - d1);
            float w11 = (1.0f - d0) * (1.0f - d1);

            float4 o;
            o.x = w00*a00.x + w10*a10.x + w01*a01.x + w11*a11.x;
            o.y = w00*a00.y + w10*a10.y + w01*a01.y + w11*a11.y;
            o.z = w00*a00.z + w10*a10.z + w01*a01.z + w11*a11.z;
            o.w = w00*a00.w + w10*a10.w + w01*a01.w + w11*a11.w;

            __stcs(reinterpret_cast<float4*>(out + p * C + 4 * k), o);
        }
    }
}

extern "C" void kernel_launch(void* const* d_in, const int* in_sizes, int n_in,
                              void* d_out, int out_size)
{
    const float2* coords  = (const float2*)d_in[0];  // [N, 2] fp32
    const float*  visible = (const float*)d_in[1];   // [H, W, C] fp32
    float* out = (float*)d_out;                      // [N, C] fp32

    int n = in_sizes[0] / 2;   // number of points
    (void)n_in; (void)out_size;

    int blocks = (n + CHUNK - 1) / CHUNK;            // 977 for n=1e6: all co-resident
    idx2pixel_fused<<<blocks, THREADS>>>(coords, visible, out, n);
}